// round 15
// baseline (speedup 1.0000x reference)
#include <cuda_runtime.h>
#include <cuda_fp16.h>
#include <cstdint>

#define NMAX 100000
#define EMAX 1600000
#define HID 128

// ---------------- scratch (device globals; no allocations allowed) ----------
__device__ uint32_t g_xgh  [(size_t)NMAX * 64];   // xg fp16, plain layout
__device__ uint32_t g_diffh[(size_t)NMAX * 64];   // diffused fp16, k-permuted
__device__ uint32_t g_evh  [(size_t)NMAX * 32];   // ev fp16, k-permuted
__device__ uint32_t g_baseh[(size_t)NMAX * 64];   // base fp16, k-permuted
__device__ int   g_deg[NMAX];
__device__ float g_dis[NMAX];
__device__ int   g_rowstart[NMAX];
__device__ int   g_cursor[NMAX];
__device__ int   g_csr[EMAX];
__device__ int   g_bsum[1024];
// fp16 transposed + k-permuted weights [128 n][K k]
__device__ __half g_wt_proj[128 * 64];
__device__ __half g_wt_gcn [128 * 128];
__device__ __half g_wt_gate[128 * 256];
__device__ __half g_wt_fuse[128 * 256];

// ---------------- PTX helpers --------------------------------------------------
__device__ __forceinline__ uint32_t smem_u32(const void* p) {
    uint32_t a;
    asm("{ .reg .u64 t; cvta.to.shared.u64 t, %1; cvt.u32.u64 %0, t; }" : "=r"(a) : "l"(p));
    return a;
}
__device__ __forceinline__ void cp16(uint32_t dst, const void* src) {
    asm volatile("cp.async.cg.shared.global [%0], [%1], 16;" :: "r"(dst), "l"(src));
}
__device__ __forceinline__ void cp_commit() {
    asm volatile("cp.async.commit_group;" ::: "memory");
}
template<int N>
__device__ __forceinline__ void cp_wait() {
    asm volatile("cp.async.wait_group %0;" :: "n"(N) : "memory");
}
__device__ __forceinline__ void mma_f16(float* c, uint32_t a0, uint32_t a1,
                                        uint32_t a2, uint32_t a3,
                                        uint32_t b0, uint32_t b1) {
    asm volatile(
        "mma.sync.aligned.m16n8k16.row.col.f32.f16.f16.f32 "
        "{%0,%1,%2,%3}, {%4,%5,%6,%7}, {%8,%9}, {%0,%1,%2,%3};"
        : "+f"(c[0]), "+f"(c[1]), "+f"(c[2]), "+f"(c[3])
        : "r"(a0), "r"(a1), "r"(a2), "r"(a3), "r"(b0), "r"(b1));
}

// k-word permutation within each 8-word group: pairs (w, w+4) become adjacent
__device__ __forceinline__ int perm8(int w) { return (w < 4) ? 2 * w : 2 * (w - 4) + 1; }
__device__ __forceinline__ int permw(int w) { return ((w >> 3) << 3) + perm8(w & 7); }

// smem geometry (uint32 words)
#define LDR 72                  // 128-half resident rows (+8 pad): conflict-free
#define LDE 40                  // 64-half resident rows (+8 pad): conflict-free
#define EF_W   (128 * LDR)      // 9216 words
#define EV_W   (128 * LDE)      // 5120 words
#define STG_W  (128 * 8)        // 1024 words: one streamed B stage
// k_proj_gcn:  ef | evR | 3 B stages | bias
#define PG_SMEM_W (EF_W + EV_W + 3 * STG_W + 128)
// k_gate_fuse: diffR(->corr) | baseR | 3 B stages | 2 biases
#define GF_SMEM_W (2 * EF_W + 3 * STG_W + 256)

// ---------------- weight prep: half Wt[n][permk(k)] = W[k][n] -------------------
__global__ void wprep(const float* __restrict__ W0, const float* __restrict__ W1,
                      const float* __restrict__ W2, const float* __restrict__ W3,
                      __half* __restrict__ T0, __half* __restrict__ T1,
                      __half* __restrict__ T2, __half* __restrict__ T3)
{
    __shared__ float s[32][33];
    int b = blockIdx.x;
    const float* W; __half* T; int K;
    if (b < 8)       { W = W0; T = T0; K = 64;  }
    else if (b < 24) { W = W1; T = T1; K = 128; b -= 8;  }
    else if (b < 56) { W = W2; T = T2; K = 256; b -= 24; }
    else             { W = W3; T = T3; K = 256; b -= 56; }
    const int k0 = (b >> 2) * 32, n0 = (b & 3) * 32;
    const int tx = threadIdx.x & 31, ty = threadIdx.x >> 5;
#pragma unroll
    for (int i = 0; i < 4; i++)
        s[ty + i * 8][tx] = W[(size_t)(k0 + ty + i * 8) * HID + n0 + tx];
    __syncthreads();
    const int k = k0 + tx;
    const int col = ((k >> 4) << 4) + (perm8((k & 15) >> 1) << 1) + (k & 1);
#pragma unroll
    for (int i = 0; i < 4; i++) {
        const int n = n0 + ty + i * 8;
        T[(size_t)n * K + col] = __float2half(s[tx][ty + i * 8]);
    }
}

// ---------------- activation convert: fp32 -> k-permuted fp16 -------------------
template<int WPR>
__global__ void cvt_half(const float2* __restrict__ in, uint32_t* __restrict__ out,
                         int total_words)
{
    int idx = blockIdx.x * blockDim.x + threadIdx.x;
    if (idx >= total_words) return;
    const int row = idx / WPR, w = idx % WPR;
    const float2 v = in[idx];
    const __half2 h = __floats2half2_rn(v.x, v.y);
    out[(size_t)row * WPR + permw(w)] = *(const uint32_t*)&h;
}

// ================================================================================
// Fused kernel 1: ef = relu(evR @ Wp + bp) [fp16 smem-resident]; xg = ef @ Wgcn
// A operands fully smem-resident; only B streams (BK=16, 3-stage).
// ================================================================================
__global__ void __launch_bounds__(256, 2)
k_proj_gcn(const uint32_t* __restrict__ evh, const __half* __restrict__ Wtp,
           const float* __restrict__ bp, const __half* __restrict__ Wtg,
           uint32_t* __restrict__ xgh, int M)
{
    extern __shared__ uint32_t dsm[];
    uint32_t* ef  = dsm;
    uint32_t* evR = dsm + EF_W;
    uint32_t* Bs  = evR + EV_W;
    float*    sb  = (float*)(Bs + 3 * STG_W);

    const int tid   = threadIdx.x;
    const int wid   = tid >> 5, lane = tid & 31;
    const int warpM = wid & 3,  warpN = wid >> 2;
    const int lr    = lane >> 2, lc = lane & 3;
    const int m0    = blockIdx.x * 128;

    if (tid < 128) sb[tid] = bp[tid];

    const uint32_t ev_b = smem_u32(evR);
    const uint32_t bs_b = smem_u32(Bs);

    float c[2][8][4];
#pragma unroll
    for (int mi = 0; mi < 2; mi++)
#pragma unroll
        for (int ni = 0; ni < 8; ni++)
#pragma unroll
            for (int j = 0; j < 4; j++) c[mi][ni][j] = 0.f;

    // ---- group 0: whole evR tile (128 rows x 32 words), 4 cp16/thread
#pragma unroll
    for (int i = 0; i < 4; i++) {
        const int slot = tid + i * 256;
        const int r = slot >> 3, q = slot & 7;
        int gr = m0 + r; if (gr > M - 1) gr = M - 1;
        cp16(ev_b + (uint32_t)(r * LDE + q * 4) * 4, evh + (size_t)gr * 32 + q * 4);
    }
    cp_commit();

    auto issueB = [&](int st, int ch, const __half* Wt, int WPRW) {
        const int n = tid >> 1, q = tid & 1;
        cp16(bs_b + (uint32_t)(st * STG_W + n * 8 + q * 4) * 4,
             Wt + (size_t)n * (WPRW * 2) + (ch * 8 + q * 4) * 2);
    };
    auto compute = [&](const uint32_t* Ab, int lda, int wb, const uint32_t* Bb) {
        uint32_t a0[2], a1[2], a2[2], a3[2];
#pragma unroll
        for (int mi = 0; mi < 2; mi++) {
            const int row = warpM * 32 + mi * 16 + lr;
            const uint2 lo = *(const uint2*)(Ab + row * lda + wb + 2 * lc);
            const uint2 hi = *(const uint2*)(Ab + (row + 8) * lda + wb + 2 * lc);
            a0[mi] = lo.x; a1[mi] = hi.x; a2[mi] = lo.y; a3[mi] = hi.y;
        }
#pragma unroll
        for (int ni = 0; ni < 8; ni++) {
            const uint2 bb = *(const uint2*)(Bb + (warpN * 64 + ni * 8 + lr) * 8 + 2 * lc);
#pragma unroll
            for (int mi = 0; mi < 2; mi++)
                mma_f16(c[mi][ni], a0[mi], a1[mi], a2[mi], a3[mi], bb.x, bb.y);
        }
    };

    // ---- phase 1: K=64, 4 B chunks, 3-stage pipeline; A = evR resident
    issueB(0, 0, Wtp, 32); cp_commit();
    issueB(1, 1, Wtp, 32); cp_commit();
    for (int i = 0; i < 4; i++) {
        if (i < 3) cp_wait<1>(); else cp_wait<0>();
        __syncthreads();
        if (i + 2 < 4) { issueB((i + 2) % 3, i + 2, Wtp, 32); cp_commit(); }
        compute(evR, LDE, i * 8, Bs + (i % 3) * STG_W);
    }
    __syncthreads();

    // prefetch phase-2 B chunks 0,1
    issueB(0, 0, Wtg, 64); cp_commit();
    issueB(1, 1, Wtg, 64); cp_commit();

    // ---- epilogue 1: relu(v+b) -> permuted fp16 into ef
#pragma unroll
    for (int mi = 0; mi < 2; mi++)
#pragma unroll
        for (int half = 0; half < 2; half++) {
            const int row = warpM * 32 + mi * 16 + lr + half * 8;
#pragma unroll
            for (int ni = 0; ni < 8; ni++) {
                const int col = warpN * 64 + ni * 8 + lc * 2;
                const float v0 = fmaxf(c[mi][ni][half * 2 + 0] + sb[col + 0], 0.f);
                const float v1 = fmaxf(c[mi][ni][half * 2 + 1] + sb[col + 1], 0.f);
                const __half2 h = __floats2half2_rn(v0, v1);
                ef[row * LDR + permw(col >> 1)] = *(const uint32_t*)&h;
            }
        }

#pragma unroll
    for (int mi = 0; mi < 2; mi++)
#pragma unroll
        for (int ni = 0; ni < 8; ni++)
#pragma unroll
            for (int j = 0; j < 4; j++) c[mi][ni][j] = 0.f;

    // ---- phase 2: xg = ef @ Wgcn, K=128 (8 chunks), A = ef resident
    for (int i = 0; i < 8; i++) {
        if (i < 7) cp_wait<1>(); else cp_wait<0>();
        __syncthreads();
        if (i + 2 < 8) { issueB((i + 2) % 3, i + 2, Wtg, 64); cp_commit(); }
        compute(ef, LDR, i * 8, Bs + (i % 3) * STG_W);
    }

    // ---- epilogue 2: xg fp16 plain layout
#pragma unroll
    for (int mi = 0; mi < 2; mi++)
#pragma unroll
        for (int half = 0; half < 2; half++) {
            const int row = m0 + warpM * 32 + mi * 16 + lr + half * 8;
            if (row >= M) continue;
#pragma unroll
            for (int ni = 0; ni < 8; ni++) {
                const int col = warpN * 64 + ni * 8 + lc * 2;
                const __half2 h = __floats2half2_rn(c[mi][ni][half * 2 + 0],
                                                    c[mi][ni][half * 2 + 1]);
                xgh[(size_t)row * 64 + (col >> 1)] = *(const uint32_t*)&h;
            }
        }
}

// ================================================================================
// Fused kernel 2: gate GEMM -> corrected (in place over diffR) -> fuse GEMM.
// baseR + diffR both smem-resident from the start; only B streams.
// ================================================================================
__global__ void __launch_bounds__(256, 2)
k_gate_fuse(const uint32_t* __restrict__ baseh, const uint32_t* __restrict__ diffh,
            const __half* __restrict__ Wtg, const float* __restrict__ bg,
            const __half* __restrict__ Wtf, const float* __restrict__ bf,
            float* __restrict__ out, int M)
{
    extern __shared__ uint32_t dsm[];
    uint32_t* diffR = dsm;              // overwritten in place by corrected
    uint32_t* baseR = dsm + EF_W;
    uint32_t* Bs    = baseR + EF_W;
    float*    sbg   = (float*)(Bs + 3 * STG_W);
    float*    sbf   = sbg + 128;

    const int tid   = threadIdx.x;
    const int wid   = tid >> 5, lane = tid & 31;
    const int warpM = wid & 3,  warpN = wid >> 2;
    const int lr    = lane >> 2, lc = lane & 3;
    const int m0    = blockIdx.x * 128;

    if (tid < 128) { sbg[tid] = bg[tid]; sbf[tid] = bf[tid]; }

    const uint32_t df_b = smem_u32(diffR);
    const uint32_t br_b = smem_u32(baseR);
    const uint32_t bs_b = smem_u32(Bs);

    float c[2][8][4];
#pragma unroll
    for (int mi = 0; mi < 2; mi++)
#pragma unroll
        for (int ni = 0; ni < 8; ni++)
#pragma unroll
            for (int j = 0; j < 4; j++) c[mi][ni][j] = 0.f;

    // ---- group 0: whole baseR + diffR tiles (8 cp16/thread each)
    {
        const int r = tid >> 1, q = tid & 1;
        int gr = m0 + r; if (gr > M - 1) gr = M - 1;
#pragma unroll
        for (int c8 = 0; c8 < 8; c8++) {
            cp16(br_b + (uint32_t)(r * LDR + c8 * 8 + q * 4) * 4,
                 baseh + (size_t)gr * 64 + c8 * 8 + q * 4);
            cp16(df_b + (uint32_t)(r * LDR + c8 * 8 + q * 4) * 4,
                 diffh + (size_t)gr * 64 + c8 * 8 + q * 4);
        }
    }
    cp_commit();

    auto issueB = [&](int ch, const __half* Wt) {
        const int n = tid >> 1, q = tid & 1;
        cp16(bs_b + (uint32_t)((ch % 3) * STG_W + n * 8 + q * 4) * 4,
             Wt + (size_t)n * 256 + (ch * 8 + q * 4) * 2);
    };
    auto compute = [&](const uint32_t* Ab, int wb, const uint32_t* Bb) {
        uint32_t a0[2], a1[2], a2[2], a3[2];
#pragma unroll
        for (int mi = 0; mi < 2; mi++) {
            const int row = warpM * 32 + mi * 16 + lr;
            const uint2 lo = *(const uint2*)(Ab + row * LDR + wb + 2 * lc);
            const uint2 hi = *(const uint2*)(Ab + (row + 8) * LDR + wb + 2 * lc);
            a0[mi] = lo.x; a1[mi] = hi.x; a2[mi] = lo.y; a3[mi] = hi.y;
        }
#pragma unroll
        for (int ni = 0; ni < 8; ni++) {
            const uint2 bb = *(const uint2*)(Bb + (warpN * 64 + ni * 8 + lr) * 8 + 2 * lc);
#pragma unroll
            for (int mi = 0; mi < 2; mi++)
                mma_f16(c[mi][ni], a0[mi], a1[mi], a2[mi], a3[mi], bb.x, bb.y);
        }
    };

    // ---- phase A: gate GEMM, K=256 (16 B chunks); A = baseR then diffR, resident
    issueB(0, Wtg); cp_commit();
    issueB(1, Wtg); cp_commit();
    for (int i = 0; i < 16; i++) {
        if (i < 15) cp_wait<1>(); else cp_wait<0>();
        __syncthreads();
        if (i + 2 < 16) { issueB(i + 2, Wtg); cp_commit(); }
        if (i < 8) compute(baseR, i * 8, Bs + (i % 3) * STG_W);
        else       compute(diffR, (i - 8) * 8, Bs + (i % 3) * STG_W);
    }
    __syncthreads();

    // prefetch fuse B chunks 0,1
    issueB(0, Wtf); cp_commit();
    issueB(1, Wtf); cp_commit();

    // ---- gate epilogue: corr = base + g*(diff-base), in place over diffR (smem)
#pragma unroll
    for (int mi = 0; mi < 2; mi++)
#pragma unroll
        for (int half = 0; half < 2; half++) {
            const int lrow = warpM * 32 + mi * 16 + lr + half * 8;
#pragma unroll
            for (int ni = 0; ni < 8; ni++) {
                const int col = warpN * 64 + ni * 8 + lc * 2;
                const int pw  = permw(col >> 1);
                const uint32_t ub = baseR[lrow * LDR + pw];
                const uint32_t ud = diffR[lrow * LDR + pw];
                const float2 b2 = __half22float2(*(const __half2*)&ub);
                const float2 d2 = __half22float2(*(const __half2*)&ud);
                const float g0 = 1.f / (1.f + __expf(-(c[mi][ni][half * 2 + 0] + sbg[col + 0])));
                const float g1 = 1.f / (1.f + __expf(-(c[mi][ni][half * 2 + 1] + sbg[col + 1])));
                const float v0 = fmaf(d2.x - b2.x, g0, b2.x);
                const float v1 = fmaf(d2.y - b2.y, g1, b2.y);
                const __half2 h = __floats2half2_rn(v0, v1);
                diffR[lrow * LDR + pw] = *(const uint32_t*)&h;
            }
        }

#pragma unroll
    for (int mi = 0; mi < 2; mi++)
#pragma unroll
        for (int ni = 0; ni < 8; ni++)
#pragma unroll
            for (int j = 0; j < 4; j++) c[mi][ni][j] = 0.f;

    // ---- phase B: fuse GEMM, K=256 (16 chunks); A = baseR then corr(diffR)
    for (int i = 0; i < 16; i++) {
        if (i < 15) cp_wait<1>(); else cp_wait<0>();
        __syncthreads();                    // orders corr writes at i=0
        if (i + 2 < 16) { issueB(i + 2, Wtf); cp_commit(); }
        if (i < 8) compute(baseR, i * 8, Bs + (i % 3) * STG_W);
        else       compute(diffR, (i - 8) * 8, Bs + (i % 3) * STG_W);
    }

    // ---- fuse epilogue: relu(v + bf) -> out (fp32)
#pragma unroll
    for (int mi = 0; mi < 2; mi++)
#pragma unroll
        for (int half = 0; half < 2; half++) {
            const int row = m0 + warpM * 32 + mi * 16 + lr + half * 8;
            if (row >= M) continue;
#pragma unroll
            for (int ni = 0; ni < 8; ni++) {
                const int col = warpN * 64 + ni * 8 + lc * 2;
                *(float2*)(out + (size_t)row * HID + col) =
                    make_float2(fmaxf(c[mi][ni][half * 2 + 0] + sbf[col + 0], 0.f),
                                fmaxf(c[mi][ni][half * 2 + 1] + sbf[col + 1], 0.f));
            }
        }
}

// ---------------- per-block edge-dtype detection --------------------------------
__device__ __forceinline__ int detect_is32(const void* ei) {
    const unsigned* p = (const unsigned*)ei;
    int any = 0;
    for (int i = threadIdx.x; i < 256; i += blockDim.x)
        any |= (p[2 * i + 1] != 0u);
    return __syncthreads_or(any);
}

// ---------------- degree / CSR (R13 proven: 1 edge/thread) -----------------------
__global__ void count_deg(const void* __restrict__ ei, int E) {
    const int is32 = detect_is32(ei);
    int e = blockIdx.x * blockDim.x + threadIdx.x;
    if (e >= E) return;
    int d = is32 ? ((const int*)ei)[(size_t)E + e]
                 : (int)((const long long*)ei)[(size_t)E + e];
    atomicAdd(&g_deg[d], 1);
}
__global__ void scan1(int n) {
    __shared__ int sh[512];
    int i = blockIdx.x * 512 + threadIdx.x;
    int v = (i < n) ? g_deg[i] : 0;
    if (i < n) g_dis[i] = rsqrtf((float)(v + 1));
    sh[threadIdx.x] = v;
    __syncthreads();
    for (int off = 256; off > 0; off >>= 1) {
        if (threadIdx.x < off) sh[threadIdx.x] += sh[threadIdx.x + off];
        __syncthreads();
    }
    if (threadIdx.x == 0) g_bsum[blockIdx.x] = sh[0];
}
__global__ void scan2(int nb) {
    __shared__ int sh[1024];
    int tid = threadIdx.x;
    int v = (tid < nb) ? g_bsum[tid] : 0;
    sh[tid] = v;
    __syncthreads();
    for (int off = 1; off < 1024; off <<= 1) {
        int t = (tid >= off) ? sh[tid - off] : 0;
        __syncthreads();
        sh[tid] += t;
        __syncthreads();
    }
    if (tid < nb) g_bsum[tid] = sh[tid] - v;
}
__global__ void scan3(int n) {
    __shared__ int sh[512];
    int tid = threadIdx.x;
    int i = blockIdx.x * 512 + tid;
    int v = (i < n) ? g_deg[i] : 0;
    sh[tid] = v;
    __syncthreads();
    for (int off = 1; off < 512; off <<= 1) {
        int t = (tid >= off) ? sh[tid - off] : 0;
        __syncthreads();
        sh[tid] += t;
        __syncthreads();
    }
    if (i < n) {
        int rs = g_bsum[blockIdx.x] + sh[tid] - v;
        g_rowstart[i] = rs;
        g_cursor[i]   = rs;
    }
}
__global__ void fill_csr(const void* __restrict__ ei, int E) {
    const int is32 = detect_is32(ei);
    int e = blockIdx.x * blockDim.x + threadIdx.x;
    if (e >= E) return;
    int s, d;
    if (is32) {
        s = ((const int*)ei)[e];
        d = ((const int*)ei)[(size_t)E + e];
    } else {
        s = (int)((const long long*)ei)[e];
        d = (int)((const long long*)ei)[(size_t)E + e];
    }
    int pos = atomicAdd(&g_cursor[d], 1);
    g_csr[pos] = s;
}

// ---------------- aggregation: warp per node, 4-way edge ILP ---------------------
__device__ __forceinline__ float4 h4f(uint2 v) {
    const float2 f0 = __half22float2(*(const __half2*)&v.x);
    const float2 f1 = __half22float2(*(const __half2*)&v.y);
    return make_float4(f0.x, f0.y, f1.x, f1.y);
}
__global__ void aggregate(const float* __restrict__ b_gcn, int n) {
    int gw   = (blockIdx.x * blockDim.x + threadIdx.x) >> 5;
    int lane = threadIdx.x & 31;
    if (gw >= n) return;
    const int node = gw;
    const uint2* __restrict__ xg2 = (const uint2*)g_xgh;

    const float4 selfv = h4f(xg2[(size_t)node * 32 + lane]);
    const float  dn    = g_dis[node];
    const int    s0    = g_rowstart[node];
    const int    cnt   = g_deg[node];

    float4 acc = make_float4(0.f, 0.f, 0.f, 0.f);
    int e = s0;
    const int eend = s0 + cnt;
    // 4 independent load chains per iteration
    for (; e + 3 < eend; e += 4) {
        const int s1 = g_csr[e],     s2 = g_csr[e + 1];
        const int s3 = g_csr[e + 2], s4 = g_csr[e + 3];
        const float w1 = g_dis[s1], w2 = g_dis[s2];
        const float w3 = g_dis[s3], w4 = g_dis[s4];
        const float4 v1 = h4f(xg2[(size_t)s1 * 32 + lane]);
        const float4 v2 = h4f(xg2[(size_t)s2 * 32 + lane]);
        const float4 v3 = h4f(xg2[(size_t)s3 * 32 + lane]);
        const float4 v4 = h4f(xg2[(size_t)s4 * 32 + lane]);
        acc.x += v1.x * w1 + v2.x * w2 + v3.x * w3 + v4.x * w4;
        acc.y += v1.y * w1 + v2.y * w2 + v3.y * w3 + v4.y * w4;
        acc.z += v1.z * w1 + v2.z * w2 + v3.z * w3 + v4.z * w4;
        acc.w += v1.w * w1 + v2.w * w2 + v3.w * w3 + v4.w * w4;
    }
    for (; e < eend; e++) {
        const int s1 = g_csr[e];
        const float w1 = g_dis[s1];
        const float4 v1 = h4f(xg2[(size_t)s1 * 32 + lane]);
        acc.x += v1.x * w1; acc.y += v1.y * w1;
        acc.z += v1.z * w1; acc.w += v1.w * w1;
    }
    const float sw = dn * dn;
    const float4 b = ((const float4*)b_gcn)[lane];
    float4 o;
    o.x = fmaxf(acc.x * dn + selfv.x * sw + b.x, 0.f);
    o.y = fmaxf(acc.y * dn + selfv.y * sw + b.y, 0.f);
    o.z = fmaxf(acc.z * dn + selfv.z * sw + b.z, 0.f);
    o.w = fmaxf(acc.w * dn + selfv.w * sw + b.w, 0.f);
    const __half2 h0 = __floats2half2_rn(o.x, o.y);
    const __half2 h1 = __floats2half2_rn(o.z, o.w);
    uint32_t* drow = g_diffh + (size_t)node * 64;
    drow[permw(2 * lane)]     = *(const uint32_t*)&h0;
    drow[permw(2 * lane + 1)] = *(const uint32_t*)&h1;
}

// ---------------- launcher --------------------------------------------------------
extern "C" void kernel_launch(void* const* d_in, const int* in_sizes, int n_in,
                              void* d_out, int out_size)
{
    const float* base   = (const float*)d_in[0];
    const float* ev     = (const float*)d_in[1];
    const void*  ei     = d_in[2];
    const float* W_proj = (const float*)d_in[3];
    const float* b_proj = (const float*)d_in[4];
    const float* W_gcn  = (const float*)d_in[5];
    const float* b_gcn  = (const float*)d_in[6];
    const float* W_gate = (const float*)d_in[7];
    const float* b_gate = (const float*)d_in[8];
    const float* W_fuse = (const float*)d_in[9];
    const float* b_fuse = (const float*)d_in[10];

    const int N = in_sizes[0] / HID;
    const int E = in_sizes[2] / 2;

    uint32_t *p_xgh, *p_diffh, *p_evh, *p_baseh;
    __half *p_wtp, *p_wtg, *p_wtga, *p_wtf;
    int *p_deg;
    cudaGetSymbolAddress((void**)&p_xgh,   g_xgh);
    cudaGetSymbolAddress((void**)&p_diffh, g_diffh);
    cudaGetSymbolAddress((void**)&p_evh,   g_evh);
    cudaGetSymbolAddress((void**)&p_baseh, g_baseh);
    cudaGetSymbolAddress((void**)&p_wtp,   g_wt_proj);
    cudaGetSymbolAddress((void**)&p_wtg,   g_wt_gcn);
    cudaGetSymbolAddress((void**)&p_wtga,  g_wt_gate);
    cudaGetSymbolAddress((void**)&p_wtf,   g_wt_fuse);
    cudaGetSymbolAddress((void**)&p_deg,   g_deg);

    cudaFuncSetAttribute(k_proj_gcn,  cudaFuncAttributeMaxDynamicSharedMemorySize, PG_SMEM_W * 4);
    cudaFuncSetAttribute(k_gate_fuse, cudaFuncAttributeMaxDynamicSharedMemorySize, GF_SMEM_W * 4);

    const int gT = (N + 127) / 128;
    const int gE = (E + 255) / 256;
    const int nb = (N + 511) / 512;

    // single side stream for CSR chain + base convert (destroyed before return)
    cudaStream_t side;
    cudaEvent_t evFork, evJoin, evJoin2;
    cudaStreamCreateWithFlags(&side, cudaStreamNonBlocking);
    cudaEventCreateWithFlags(&evFork,  cudaEventDisableTiming);
    cudaEventCreateWithFlags(&evJoin,  cudaEventDisableTiming);
    cudaEventCreateWithFlags(&evJoin2, cudaEventDisableTiming);

    cudaEventRecord(evFork, 0);
    cudaStreamWaitEvent(side, evFork, 0);

    // --- side: CSR build, then base convert (joined separately)
    cudaMemsetAsync(p_deg, 0, (size_t)N * sizeof(int), side);
    count_deg<<<gE, 256, 0, side>>>(ei, E);
    scan1<<<nb, 512, 0, side>>>(N);
    scan2<<<1, 1024, 0, side>>>(nb);
    scan3<<<nb, 512, 0, side>>>(N);
    fill_csr<<<gE, 256, 0, side>>>(ei, E);
    cudaEventRecord(evJoin, side);                      // CSR ready
    cvt_half<64><<<(N * 64 + 255) / 256, 256, 0, side>>>((const float2*)base, p_baseh, N * 64);
    cudaEventRecord(evJoin2, side);                     // baseh ready

    // --- main: weight prep + ev convert + fused proj/gcn GEMM (overlaps side)
    wprep<<<88, 256>>>(W_proj, W_gcn, W_gate, W_fuse, p_wtp, p_wtg, p_wtga, p_wtf);
    cvt_half<32><<<(N * 32 + 255) / 256, 256>>>((const float2*)ev, p_evh, N * 32);
    k_proj_gcn<<<gT, 256, PG_SMEM_W * 4>>>(p_evh, p_wtp, b_proj, p_wtg, p_xgh, N);

    // aggregate needs xgh (main) + CSR (side); overlaps cvt_base on the side stream
    cudaStreamWaitEvent(0, evJoin, 0);
    aggregate<<<(N * 32 + 255) / 256, 256>>>(b_gcn, N);

    // gate_fuse additionally needs baseh
    cudaStreamWaitEvent(0, evJoin2, 0);
    k_gate_fuse<<<gT, 256, GF_SMEM_W * 4>>>(p_baseh, p_diffh, p_wtga, b_gate,
                                            p_wtf, b_fuse, (float*)d_out, N);

    // release resources created this call (graph retains captured dependencies)
    cudaEventDestroy(evFork);
    cudaEventDestroy(evJoin);
    cudaEventDestroy(evJoin2);
    cudaStreamDestroy(side);
}

// round 16
// speedup vs baseline: 1.0360x; 1.0360x over previous
#include <cuda_runtime.h>
#include <cuda_fp16.h>
#include <cstdint>

#define NMAX 100000
#define EMAX 1600000
#define HID 128

// ---------------- scratch (device globals; no allocations allowed) ----------
__device__ uint32_t g_xgh  [(size_t)NMAX * 64];   // xg fp16, plain layout
__device__ uint32_t g_diffh[(size_t)NMAX * 64];   // diffused fp16, k-permuted
__device__ uint32_t g_baseh[(size_t)NMAX * 64];   // base fp16, k-permuted
__device__ int   g_deg[NMAX];
__device__ float g_dis[NMAX];
__device__ int   g_rowstart[NMAX];
__device__ int   g_cursor[NMAX];
__device__ int   g_csr[EMAX];
__device__ int   g_bsum[1024];
// fp16 transposed + k-permuted weights [128 n][K k]
__device__ __half g_wt_proj[128 * 64];
__device__ __half g_wt_gcn [128 * 128];
__device__ __half g_wt_gate[128 * 256];
__device__ __half g_wt_fuse[128 * 256];

// ---------------- PTX helpers --------------------------------------------------
__device__ __forceinline__ uint32_t smem_u32(const void* p) {
    uint32_t a;
    asm("{ .reg .u64 t; cvta.to.shared.u64 t, %1; cvt.u32.u64 %0, t; }" : "=r"(a) : "l"(p));
    return a;
}
__device__ __forceinline__ void cp16(uint32_t dst, const void* src) {
    asm volatile("cp.async.cg.shared.global [%0], [%1], 16;" :: "r"(dst), "l"(src));
}
__device__ __forceinline__ void cp_commit() {
    asm volatile("cp.async.commit_group;" ::: "memory");
}
template<int N>
__device__ __forceinline__ void cp_wait() {
    asm volatile("cp.async.wait_group %0;" :: "n"(N) : "memory");
}
__device__ __forceinline__ void mma_f16(float* c, uint32_t a0, uint32_t a1,
                                        uint32_t a2, uint32_t a3,
                                        uint32_t b0, uint32_t b1) {
    asm volatile(
        "mma.sync.aligned.m16n8k16.row.col.f32.f16.f16.f32 "
        "{%0,%1,%2,%3}, {%4,%5,%6,%7}, {%8,%9}, {%0,%1,%2,%3};"
        : "+f"(c[0]), "+f"(c[1]), "+f"(c[2]), "+f"(c[3])
        : "r"(a0), "r"(a1), "r"(a2), "r"(a3), "r"(b0), "r"(b1));
}

// k-word permutation within each 8-word group: pairs (w, w+4) become adjacent
__device__ __forceinline__ int perm8(int w) { return (w < 4) ? 2 * w : 2 * (w - 4) + 1; }
__device__ __forceinline__ int permw(int w) { return ((w >> 3) << 3) + perm8(w & 7); }

// smem geometry (uint32 words)
#define LDR 72                  // 128-half resident rows (+8 pad): conflict-free
#define LDE 40                  // 64-half resident rows (+8 pad): conflict-free
#define EF_W   (128 * LDR)      // 9216 words
#define EV_W   (128 * LDE)      // 5120 words
#define STG_W  (128 * 8)        // 1024 words: one streamed B stage
// k_proj_gcn:  ef | evR | 3 B stages | bias
#define PG_SMEM_W (EF_W + EV_W + 3 * STG_W + 128)
// k_gate_fuse: diffR(->corr) | baseR | 3 B stages | 2 biases
#define GF_SMEM_W (2 * EF_W + 3 * STG_W + 256)

// ---------------- weight prep: half Wt[n][permk(k)] = W[k][n] -------------------
__global__ void wprep(const float* __restrict__ W0, const float* __restrict__ W1,
                      const float* __restrict__ W2, const float* __restrict__ W3,
                      __half* __restrict__ T0, __half* __restrict__ T1,
                      __half* __restrict__ T2, __half* __restrict__ T3)
{
    __shared__ float s[32][33];
    int b = blockIdx.x;
    const float* W; __half* T; int K;
    if (b < 8)       { W = W0; T = T0; K = 64;  }
    else if (b < 24) { W = W1; T = T1; K = 128; b -= 8;  }
    else if (b < 56) { W = W2; T = T2; K = 256; b -= 24; }
    else             { W = W3; T = T3; K = 256; b -= 56; }
    const int k0 = (b >> 2) * 32, n0 = (b & 3) * 32;
    const int tx = threadIdx.x & 31, ty = threadIdx.x >> 5;
#pragma unroll
    for (int i = 0; i < 4; i++)
        s[ty + i * 8][tx] = W[(size_t)(k0 + ty + i * 8) * HID + n0 + tx];
    __syncthreads();
    const int k = k0 + tx;
    const int col = ((k >> 4) << 4) + (perm8((k & 15) >> 1) << 1) + (k & 1);
#pragma unroll
    for (int i = 0; i < 4; i++) {
        const int n = n0 + ty + i * 8;
        T[(size_t)n * K + col] = __float2half(s[tx][ty + i * 8]);
    }
}

// ---------------- activation convert: fp32 -> k-permuted fp16 (base only) -------
template<int WPR>
__global__ void cvt_half(const float2* __restrict__ in, uint32_t* __restrict__ out,
                         int total_words)
{
    int idx = blockIdx.x * blockDim.x + threadIdx.x;
    if (idx >= total_words) return;
    const int row = idx / WPR, w = idx % WPR;
    const float2 v = in[idx];
    const __half2 h = __floats2half2_rn(v.x, v.y);
    out[(size_t)row * WPR + permw(w)] = *(const uint32_t*)&h;
}

// ================================================================================
// Fused kernel 1: ef = relu(evR @ Wp + bp) [fp16 smem-resident]; xg = ef @ Wgcn
// ev is converted fp32->fp16 in the prologue (no separate cvt kernel, no round-trip)
// ================================================================================
__global__ void __launch_bounds__(256, 2)
k_proj_gcn(const float* __restrict__ ev, const __half* __restrict__ Wtp,
           const float* __restrict__ bp, const __half* __restrict__ Wtg,
           uint32_t* __restrict__ xgh, int M)
{
    extern __shared__ uint32_t dsm[];
    uint32_t* ef  = dsm;
    uint32_t* evR = dsm + EF_W;
    uint32_t* Bs  = evR + EV_W;
    float*    sb  = (float*)(Bs + 3 * STG_W);

    const int tid   = threadIdx.x;
    const int wid   = tid >> 5, lane = tid & 31;
    const int warpM = wid & 3,  warpN = wid >> 2;
    const int lr    = lane >> 2, lc = lane & 3;
    const int m0    = blockIdx.x * 128;

    if (tid < 128) sb[tid] = bp[tid];

    const uint32_t bs_b = smem_u32(Bs);

    float c[2][8][4];
#pragma unroll
    for (int mi = 0; mi < 2; mi++)
#pragma unroll
        for (int ni = 0; ni < 8; ni++)
#pragma unroll
            for (int j = 0; j < 4; j++) c[mi][ni][j] = 0.f;

    auto issueB = [&](int st, int ch, const __half* Wt, int WPRW) {
        const int n = tid >> 1, q = tid & 1;
        cp16(bs_b + (uint32_t)(st * STG_W + n * 8 + q * 4) * 4,
             Wt + (size_t)n * (WPRW * 2) + (ch * 8 + q * 4) * 2);
    };

    // ---- B prefetch first (cp.async proceeds while we LDG-convert ev below)
    issueB(0, 0, Wtp, 32); cp_commit();
    issueB(1, 1, Wtp, 32); cp_commit();

    // ---- prologue: load fp32 ev tile, convert to permuted fp16 evR
#pragma unroll
    for (int i = 0; i < 4; i++) {
        const int slot = tid + i * 256;
        const int r = slot >> 3, q = slot & 7;       // 8 slots per 32-word row
        int gr = m0 + r; if (gr > M - 1) gr = M - 1;
        const float4 f0 = *(const float4*)(ev + (size_t)gr * 64 + q * 8);
        const float4 f1 = *(const float4*)(ev + (size_t)gr * 64 + q * 8 + 4);
        const __half2 h0 = __floats2half2_rn(f0.x, f0.y);
        const __half2 h1 = __floats2half2_rn(f0.z, f0.w);
        const __half2 h2 = __floats2half2_rn(f1.x, f1.y);
        const __half2 h3 = __floats2half2_rn(f1.z, f1.w);
        evR[r * LDE + permw(q * 4 + 0)] = *(const uint32_t*)&h0;
        evR[r * LDE + permw(q * 4 + 1)] = *(const uint32_t*)&h1;
        evR[r * LDE + permw(q * 4 + 2)] = *(const uint32_t*)&h2;
        evR[r * LDE + permw(q * 4 + 3)] = *(const uint32_t*)&h3;
    }

    auto compute = [&](const uint32_t* Ab, int lda, int wb, const uint32_t* Bb) {
        uint32_t a0[2], a1[2], a2[2], a3[2];
#pragma unroll
        for (int mi = 0; mi < 2; mi++) {
            const int row = warpM * 32 + mi * 16 + lr;
            const uint2 lo = *(const uint2*)(Ab + row * lda + wb + 2 * lc);
            const uint2 hi = *(const uint2*)(Ab + (row + 8) * lda + wb + 2 * lc);
            a0[mi] = lo.x; a1[mi] = hi.x; a2[mi] = lo.y; a3[mi] = hi.y;
        }
#pragma unroll
        for (int ni = 0; ni < 8; ni++) {
            const uint2 bb = *(const uint2*)(Bb + (warpN * 64 + ni * 8 + lr) * 8 + 2 * lc);
#pragma unroll
            for (int mi = 0; mi < 2; mi++)
                mma_f16(c[mi][ni], a0[mi], a1[mi], a2[mi], a3[mi], bb.x, bb.y);
        }
    };

    // ---- phase 1: K=64, 4 B chunks, 3-stage pipeline; A = evR resident
    for (int i = 0; i < 4; i++) {
        if (i < 3) cp_wait<1>(); else cp_wait<0>();
        __syncthreads();                          // also publishes evR stores at i=0
        if (i + 2 < 4) { issueB((i + 2) % 3, i + 2, Wtp, 32); cp_commit(); }
        compute(evR, LDE, i * 8, Bs + (i % 3) * STG_W);
    }
    __syncthreads();

    // prefetch phase-2 B chunks 0,1
    issueB(0, 0, Wtg, 64); cp_commit();
    issueB(1, 1, Wtg, 64); cp_commit();

    // ---- epilogue 1: relu(v+b) -> permuted fp16 into ef
#pragma unroll
    for (int mi = 0; mi < 2; mi++)
#pragma unroll
        for (int half = 0; half < 2; half++) {
            const int row = warpM * 32 + mi * 16 + lr + half * 8;
#pragma unroll
            for (int ni = 0; ni < 8; ni++) {
                const int col = warpN * 64 + ni * 8 + lc * 2;
                const float v0 = fmaxf(c[mi][ni][half * 2 + 0] + sb[col + 0], 0.f);
                const float v1 = fmaxf(c[mi][ni][half * 2 + 1] + sb[col + 1], 0.f);
                const __half2 h = __floats2half2_rn(v0, v1);
                ef[row * LDR + permw(col >> 1)] = *(const uint32_t*)&h;
            }
        }

#pragma unroll
    for (int mi = 0; mi < 2; mi++)
#pragma unroll
        for (int ni = 0; ni < 8; ni++)
#pragma unroll
            for (int j = 0; j < 4; j++) c[mi][ni][j] = 0.f;

    // ---- phase 2: xg = ef @ Wgcn, K=128 (8 chunks), A = ef resident
    for (int i = 0; i < 8; i++) {
        if (i < 7) cp_wait<1>(); else cp_wait<0>();
        __syncthreads();
        if (i + 2 < 8) { issueB((i + 2) % 3, i + 2, Wtg, 64); cp_commit(); }
        compute(ef, LDR, i * 8, Bs + (i % 3) * STG_W);
    }

    // ---- epilogue 2: xg fp16 plain layout
#pragma unroll
    for (int mi = 0; mi < 2; mi++)
#pragma unroll
        for (int half = 0; half < 2; half++) {
            const int row = m0 + warpM * 32 + mi * 16 + lr + half * 8;
            if (row >= M) continue;
#pragma unroll
            for (int ni = 0; ni < 8; ni++) {
                const int col = warpN * 64 + ni * 8 + lc * 2;
                const __half2 h = __floats2half2_rn(c[mi][ni][half * 2 + 0],
                                                    c[mi][ni][half * 2 + 1]);
                xgh[(size_t)row * 64 + (col >> 1)] = *(const uint32_t*)&h;
            }
        }
}

// ================================================================================
// Fused kernel 2: gate GEMM -> corrected (in place over diffR) -> fuse GEMM.
// baseR + diffR both smem-resident from the start; only B streams.
// ================================================================================
__global__ void __launch_bounds__(256, 2)
k_gate_fuse(const uint32_t* __restrict__ baseh, const uint32_t* __restrict__ diffh,
            const __half* __restrict__ Wtg, const float* __restrict__ bg,
            const __half* __restrict__ Wtf, const float* __restrict__ bf,
            float* __restrict__ out, int M)
{
    extern __shared__ uint32_t dsm[];
    uint32_t* diffR = dsm;              // overwritten in place by corrected
    uint32_t* baseR = dsm + EF_W;
    uint32_t* Bs    = baseR + EF_W;
    float*    sbg   = (float*)(Bs + 3 * STG_W);
    float*    sbf   = sbg + 128;

    const int tid   = threadIdx.x;
    const int wid   = tid >> 5, lane = tid & 31;
    const int warpM = wid & 3,  warpN = wid >> 2;
    const int lr    = lane >> 2, lc = lane & 3;
    const int m0    = blockIdx.x * 128;

    if (tid < 128) { sbg[tid] = bg[tid]; sbf[tid] = bf[tid]; }

    const uint32_t df_b = smem_u32(diffR);
    const uint32_t br_b = smem_u32(baseR);
    const uint32_t bs_b = smem_u32(Bs);

    float c[2][8][4];
#pragma unroll
    for (int mi = 0; mi < 2; mi++)
#pragma unroll
        for (int ni = 0; ni < 8; ni++)
#pragma unroll
            for (int j = 0; j < 4; j++) c[mi][ni][j] = 0.f;

    // ---- group 0: whole baseR + diffR tiles (8 cp16/thread each)
    {
        const int r = tid >> 1, q = tid & 1;
        int gr = m0 + r; if (gr > M - 1) gr = M - 1;
#pragma unroll
        for (int c8 = 0; c8 < 8; c8++) {
            cp16(br_b + (uint32_t)(r * LDR + c8 * 8 + q * 4) * 4,
                 baseh + (size_t)gr * 64 + c8 * 8 + q * 4);
            cp16(df_b + (uint32_t)(r * LDR + c8 * 8 + q * 4) * 4,
                 diffh + (size_t)gr * 64 + c8 * 8 + q * 4);
        }
    }
    cp_commit();

    auto issueB = [&](int ch, const __half* Wt) {
        const int n = tid >> 1, q = tid & 1;
        cp16(bs_b + (uint32_t)((ch % 3) * STG_W + n * 8 + q * 4) * 4,
             Wt + (size_t)n * 256 + (ch * 8 + q * 4) * 2);
    };
    auto compute = [&](const uint32_t* Ab, int wb, const uint32_t* Bb) {
        uint32_t a0[2], a1[2], a2[2], a3[2];
#pragma unroll
        for (int mi = 0; mi < 2; mi++) {
            const int row = warpM * 32 + mi * 16 + lr;
            const uint2 lo = *(const uint2*)(Ab + row * LDR + wb + 2 * lc);
            const uint2 hi = *(const uint2*)(Ab + (row + 8) * LDR + wb + 2 * lc);
            a0[mi] = lo.x; a1[mi] = hi.x; a2[mi] = lo.y; a3[mi] = hi.y;
        }
#pragma unroll
        for (int ni = 0; ni < 8; ni++) {
            const uint2 bb = *(const uint2*)(Bb + (warpN * 64 + ni * 8 + lr) * 8 + 2 * lc);
#pragma unroll
            for (int mi = 0; mi < 2; mi++)
                mma_f16(c[mi][ni], a0[mi], a1[mi], a2[mi], a3[mi], bb.x, bb.y);
        }
    };

    // ---- phase A: gate GEMM, K=256 (16 B chunks); A = baseR then diffR, resident
    issueB(0, Wtg); cp_commit();
    issueB(1, Wtg); cp_commit();
    for (int i = 0; i < 16; i++) {
        if (i < 15) cp_wait<1>(); else cp_wait<0>();
        __syncthreads();
        if (i + 2 < 16) { issueB(i + 2, Wtg); cp_commit(); }
        if (i < 8) compute(baseR, i * 8, Bs + (i % 3) * STG_W);
        else       compute(diffR, (i - 8) * 8, Bs + (i % 3) * STG_W);
    }
    __syncthreads();

    // prefetch fuse B chunks 0,1
    issueB(0, Wtf); cp_commit();
    issueB(1, Wtf); cp_commit();

    // ---- gate epilogue: corr = base + g*(diff-base), in place over diffR (smem)
#pragma unroll
    for (int mi = 0; mi < 2; mi++)
#pragma unroll
        for (int half = 0; half < 2; half++) {
            const int lrow = warpM * 32 + mi * 16 + lr + half * 8;
#pragma unroll
            for (int ni = 0; ni < 8; ni++) {
                const int col = warpN * 64 + ni * 8 + lc * 2;
                const int pw  = permw(col >> 1);
                const uint32_t ub = baseR[lrow * LDR + pw];
                const uint32_t ud = diffR[lrow * LDR + pw];
                const float2 b2 = __half22float2(*(const __half2*)&ub);
                const float2 d2 = __half22float2(*(const __half2*)&ud);
                const float g0 = 1.f / (1.f + __expf(-(c[mi][ni][half * 2 + 0] + sbg[col + 0])));
                const float g1 = 1.f / (1.f + __expf(-(c[mi][ni][half * 2 + 1] + sbg[col + 1])));
                const float v0 = fmaf(d2.x - b2.x, g0, b2.x);
                const float v1 = fmaf(d2.y - b2.y, g1, b2.y);
                const __half2 h = __floats2half2_rn(v0, v1);
                diffR[lrow * LDR + pw] = *(const uint32_t*)&h;
            }
        }

#pragma unroll
    for (int mi = 0; mi < 2; mi++)
#pragma unroll
        for (int ni = 0; ni < 8; ni++)
#pragma unroll
            for (int j = 0; j < 4; j++) c[mi][ni][j] = 0.f;

    // ---- phase B: fuse GEMM, K=256 (16 chunks); A = baseR then corr(diffR)
    for (int i = 0; i < 16; i++) {
        if (i < 15) cp_wait<1>(); else cp_wait<0>();
        __syncthreads();                    // orders corr writes at i=0
        if (i + 2 < 16) { issueB(i + 2, Wtf); cp_commit(); }
        if (i < 8) compute(baseR, i * 8, Bs + (i % 3) * STG_W);
        else       compute(diffR, (i - 8) * 8, Bs + (i % 3) * STG_W);
    }

    // ---- fuse epilogue: relu(v + bf) -> out (fp32)
#pragma unroll
    for (int mi = 0; mi < 2; mi++)
#pragma unroll
        for (int half = 0; half < 2; half++) {
            const int row = m0 + warpM * 32 + mi * 16 + lr + half * 8;
            if (row >= M) continue;
#pragma unroll
            for (int ni = 0; ni < 8; ni++) {
                const int col = warpN * 64 + ni * 8 + lc * 2;
                *(float2*)(out + (size_t)row * HID + col) =
                    make_float2(fmaxf(c[mi][ni][half * 2 + 0] + sbf[col + 0], 0.f),
                                fmaxf(c[mi][ni][half * 2 + 1] + sbf[col + 1], 0.f));
            }
        }
}

// ---------------- per-block edge-dtype detection --------------------------------
__device__ __forceinline__ int detect_is32(const void* ei) {
    const unsigned* p = (const unsigned*)ei;
    int any = 0;
    for (int i = threadIdx.x; i < 256; i += blockDim.x)
        any |= (p[2 * i + 1] != 0u);
    return __syncthreads_or(any);
}

// ---------------- degree / CSR (1 edge/thread — atomic-parallel) ------------------
__global__ void count_deg(const void* __restrict__ ei, int E) {
    const int is32 = detect_is32(ei);
    int e = blockIdx.x * blockDim.x + threadIdx.x;
    if (e >= E) return;
    int d = is32 ? ((const int*)ei)[(size_t)E + e]
                 : (int)((const long long*)ei)[(size_t)E + e];
    atomicAdd(&g_deg[d], 1);
}
__global__ void scan1(int n) {
    __shared__ int sh[512];
    int i = blockIdx.x * 512 + threadIdx.x;
    int v = (i < n) ? g_deg[i] : 0;
    if (i < n) g_dis[i] = rsqrtf((float)(v + 1));
    sh[threadIdx.x] = v;
    __syncthreads();
    for (int off = 256; off > 0; off >>= 1) {
        if (threadIdx.x < off) sh[threadIdx.x] += sh[threadIdx.x + off];
        __syncthreads();
    }
    if (threadIdx.x == 0) g_bsum[blockIdx.x] = sh[0];
}
__global__ void scan2(int nb) {
    __shared__ int sh[1024];
    int tid = threadIdx.x;
    int v = (tid < nb) ? g_bsum[tid] : 0;
    sh[tid] = v;
    __syncthreads();
    for (int off = 1; off < 1024; off <<= 1) {
        int t = (tid >= off) ? sh[tid - off] : 0;
        __syncthreads();
        sh[tid] += t;
        __syncthreads();
    }
    if (tid < nb) g_bsum[tid] = sh[tid] - v;
}
__global__ void scan3(int n) {
    __shared__ int sh[512];
    int tid = threadIdx.x;
    int i = blockIdx.x * 512 + tid;
    int v = (i < n) ? g_deg[i] : 0;
    sh[tid] = v;
    __syncthreads();
    for (int off = 1; off < 512; off <<= 1) {
        int t = (tid >= off) ? sh[tid - off] : 0;
        __syncthreads();
        sh[tid] += t;
        __syncthreads();
    }
    if (i < n) {
        int rs = g_bsum[blockIdx.x] + sh[tid] - v;
        g_rowstart[i] = rs;
        g_cursor[i]   = rs;
    }
}
__global__ void fill_csr(const void* __restrict__ ei, int E) {
    const int is32 = detect_is32(ei);
    int e = blockIdx.x * blockDim.x + threadIdx.x;
    if (e >= E) return;
    int s, d;
    if (is32) {
        s = ((const int*)ei)[e];
        d = ((const int*)ei)[(size_t)E + e];
    } else {
        s = (int)((const long long*)ei)[e];
        d = (int)((const long long*)ei)[(size_t)E + e];
    }
    int pos = atomicAdd(&g_cursor[d], 1);
    g_csr[pos] = s;
}

// ---------------- aggregation: warp per node, 2-way edge ILP (R13 champion) ------
__device__ __forceinline__ float4 h4f(uint2 v) {
    const float2 f0 = __half22float2(*(const __half2*)&v.x);
    const float2 f1 = __half22float2(*(const __half2*)&v.y);
    return make_float4(f0.x, f0.y, f1.x, f1.y);
}
__global__ void aggregate(const float* __restrict__ b_gcn, int n) {
    int gw   = (blockIdx.x * blockDim.x + threadIdx.x) >> 5;
    int lane = threadIdx.x & 31;
    if (gw >= n) return;
    const int node = gw;
    const uint2* __restrict__ xg2 = (const uint2*)g_xgh;

    const float4 selfv = h4f(xg2[(size_t)node * 32 + lane]);
    const float  dn    = g_dis[node];
    const int    s0    = g_rowstart[node];
    const int    cnt   = g_deg[node];

    float4 acc = make_float4(0.f, 0.f, 0.f, 0.f);
    int e = s0, eend = s0 + cnt;
    for (; e + 1 < eend; e += 2) {
        const int s1 = g_csr[e], s2 = g_csr[e + 1];
        const float w1 = g_dis[s1], w2 = g_dis[s2];
        const float4 v1 = h4f(xg2[(size_t)s1 * 32 + lane]);
        const float4 v2 = h4f(xg2[(size_t)s2 * 32 + lane]);
        acc.x += v1.x * w1 + v2.x * w2;
        acc.y += v1.y * w1 + v2.y * w2;
        acc.z += v1.z * w1 + v2.z * w2;
        acc.w += v1.w * w1 + v2.w * w2;
    }
    if (e < eend) {
        const int s1 = g_csr[e];
        const float w1 = g_dis[s1];
        const float4 v1 = h4f(xg2[(size_t)s1 * 32 + lane]);
        acc.x += v1.x * w1; acc.y += v1.y * w1;
        acc.z += v1.z * w1; acc.w += v1.w * w1;
    }
    const float sw = dn * dn;
    const float4 b = ((const float4*)b_gcn)[lane];
    float4 o;
    o.x = fmaxf(acc.x * dn + selfv.x * sw + b.x, 0.f);
    o.y = fmaxf(acc.y * dn + selfv.y * sw + b.y, 0.f);
    o.z = fmaxf(acc.z * dn + selfv.z * sw + b.z, 0.f);
    o.w = fmaxf(acc.w * dn + selfv.w * sw + b.w, 0.f);
    const __half2 h0 = __floats2half2_rn(o.x, o.y);
    const __half2 h1 = __floats2half2_rn(o.z, o.w);
    uint32_t* drow = g_diffh + (size_t)node * 64;
    drow[permw(2 * lane)]     = *(const uint32_t*)&h0;
    drow[permw(2 * lane + 1)] = *(const uint32_t*)&h1;
}

// ---------------- launcher --------------------------------------------------------
extern "C" void kernel_launch(void* const* d_in, const int* in_sizes, int n_in,
                              void* d_out, int out_size)
{
    const float* base   = (const float*)d_in[0];
    const float* ev     = (const float*)d_in[1];
    const void*  ei     = d_in[2];
    const float* W_proj = (const float*)d_in[3];
    const float* b_proj = (const float*)d_in[4];
    const float* W_gcn  = (const float*)d_in[5];
    const float* b_gcn  = (const float*)d_in[6];
    const float* W_gate = (const float*)d_in[7];
    const float* b_gate = (const float*)d_in[8];
    const float* W_fuse = (const float*)d_in[9];
    const float* b_fuse = (const float*)d_in[10];

    const int N = in_sizes[0] / HID;
    const int E = in_sizes[2] / 2;

    uint32_t *p_xgh, *p_diffh, *p_baseh;
    __half *p_wtp, *p_wtg, *p_wtga, *p_wtf;
    int *p_deg;
    cudaGetSymbolAddress((void**)&p_xgh,   g_xgh);
    cudaGetSymbolAddress((void**)&p_diffh, g_diffh);
    cudaGetSymbolAddress((void**)&p_baseh, g_baseh);
    cudaGetSymbolAddress((void**)&p_wtp,   g_wt_proj);
    cudaGetSymbolAddress((void**)&p_wtg,   g_wt_gcn);
    cudaGetSymbolAddress((void**)&p_wtga,  g_wt_gate);
    cudaGetSymbolAddress((void**)&p_wtf,   g_wt_fuse);
    cudaGetSymbolAddress((void**)&p_deg,   g_deg);

    cudaFuncSetAttribute(k_proj_gcn,  cudaFuncAttributeMaxDynamicSharedMemorySize, PG_SMEM_W * 4);
    cudaFuncSetAttribute(k_gate_fuse, cudaFuncAttributeMaxDynamicSharedMemorySize, GF_SMEM_W * 4);

    const int gT = (N + 127) / 128;
    const int gE = (E + 255) / 256;
    const int nb = (N + 511) / 512;

    // single side stream for CSR chain + base convert (destroyed before return)
    cudaStream_t side;
    cudaEvent_t evFork, evJoin, evJoin2;
    cudaStreamCreateWithFlags(&side, cudaStreamNonBlocking);
    cudaEventCreateWithFlags(&evFork,  cudaEventDisableTiming);
    cudaEventCreateWithFlags(&evJoin,  cudaEventDisableTiming);
    cudaEventCreateWithFlags(&evJoin2, cudaEventDisableTiming);

    cudaEventRecord(evFork, 0);
    cudaStreamWaitEvent(side, evFork, 0);

    // --- side: CSR build, then base convert (joined separately)
    cudaMemsetAsync(p_deg, 0, (size_t)N * sizeof(int), side);
    count_deg<<<gE, 256, 0, side>>>(ei, E);
    scan1<<<nb, 512, 0, side>>>(N);
    scan2<<<1, 1024, 0, side>>>(nb);
    scan3<<<nb, 512, 0, side>>>(N);
    fill_csr<<<gE, 256, 0, side>>>(ei, E);
    cudaEventRecord(evJoin, side);                      // CSR ready
    cvt_half<64><<<(N * 64 + 255) / 256, 256, 0, side>>>((const float2*)base, p_baseh, N * 64);
    cudaEventRecord(evJoin2, side);                     // baseh ready

    // --- main: weight prep + fused proj/gcn GEMM (ev converted in-kernel)
    wprep<<<88, 256>>>(W_proj, W_gcn, W_gate, W_fuse, p_wtp, p_wtg, p_wtga, p_wtf);
    k_proj_gcn<<<gT, 256, PG_SMEM_W * 4>>>(ev, p_wtp, b_proj, p_wtg, p_xgh, N);

    // aggregate needs xgh (main) + CSR (side); overlaps cvt_base on the side stream
    cudaStreamWaitEvent(0, evJoin, 0);
    aggregate<<<(N * 32 + 255) / 256, 256>>>(b_gcn, N);

    // gate_fuse additionally needs baseh
    cudaStreamWaitEvent(0, evJoin2, 0);
    k_gate_fuse<<<gT, 256, GF_SMEM_W * 4>>>(p_baseh, p_diffh, p_wtga, b_gate,
                                            p_wtf, b_fuse, (float*)d_out, N);

    // release resources created this call (graph retains captured dependencies)
    cudaEventDestroy(evFork);
    cudaEventDestroy(evJoin);
    cudaEventDestroy(evJoin2);
    cudaStreamDestroy(side);
}

// round 17
// speedup vs baseline: 1.0659x; 1.0289x over previous
#include <cuda_runtime.h>
#include <cuda_fp16.h>
#include <cstdint>

#define NMAX 100000
#define EMAX 1600000
#define HID 128

// ---------------- scratch (device globals; no allocations allowed) ----------
__device__ uint32_t g_xgh  [(size_t)NMAX * 64];   // xg fp16, plain layout
__device__ uint32_t g_diffh[(size_t)NMAX * 64];   // diffused fp16, k-permuted
__device__ uint32_t g_baseh[(size_t)NMAX * 64];   // base fp16, k-permuted
__device__ int   g_deg[NMAX];
__device__ float g_dis[NMAX];
__device__ int   g_rowstart[NMAX];
__device__ int   g_cursor[NMAX];
__device__ int   g_csr[EMAX];
__device__ int   g_bsum[1024];
// fp16 transposed + k-permuted weights [128 n][K k]
__device__ __half g_wt_proj[128 * 64];
__device__ __half g_wt_gcn [128 * 128];
__device__ __half g_wt_gate[128 * 256];
__device__ __half g_wt_fuse[128 * 256];

// ---------------- PTX helpers --------------------------------------------------
__device__ __forceinline__ uint32_t smem_u32(const void* p) {
    uint32_t a;
    asm("{ .reg .u64 t; cvta.to.shared.u64 t, %1; cvt.u32.u64 %0, t; }" : "=r"(a) : "l"(p));
    return a;
}
__device__ __forceinline__ void cp16(uint32_t dst, const void* src) {
    asm volatile("cp.async.cg.shared.global [%0], [%1], 16;" :: "r"(dst), "l"(src));
}
__device__ __forceinline__ void cp_commit() {
    asm volatile("cp.async.commit_group;" ::: "memory");
}
template<int N>
__device__ __forceinline__ void cp_wait() {
    asm volatile("cp.async.wait_group %0;" :: "n"(N) : "memory");
}
__device__ __forceinline__ void mma_f16(float* c, uint32_t a0, uint32_t a1,
                                        uint32_t a2, uint32_t a3,
                                        uint32_t b0, uint32_t b1) {
    asm volatile(
        "mma.sync.aligned.m16n8k16.row.col.f32.f16.f16.f32 "
        "{%0,%1,%2,%3}, {%4,%5,%6,%7}, {%8,%9}, {%0,%1,%2,%3};"
        : "+f"(c[0]), "+f"(c[1]), "+f"(c[2]), "+f"(c[3])
        : "r"(a0), "r"(a1), "r"(a2), "r"(a3), "r"(b0), "r"(b1));
}

// k-word permutation within each 8-word group: pairs (w, w+4) become adjacent
__device__ __forceinline__ int perm8(int w) { return (w < 4) ? 2 * w : 2 * (w - 4) + 1; }
__device__ __forceinline__ int permw(int w) { return ((w >> 3) << 3) + perm8(w & 7); }

// smem geometry (uint32 words)
#define LDR 72                  // 128-half resident rows (+8 pad): conflict-free
#define LDE 40                  // 64-half resident rows (+8 pad): conflict-free
#define EF_W   (128 * LDR)      // 9216 words
#define EV_W   (128 * LDE)      // 5120 words
#define STG_W  (128 * 8)        // 1024 words: one BK=16 sub-tile
#define CH32_W (2 * STG_W)      // 2048 words: one BK=32 stage (2 sub-tiles)
// k_proj_gcn:  ef | evR | 3 B stages (BK=16) | bias
#define PG_SMEM_W (EF_W + EV_W + 3 * STG_W + 128)
// k_gate_fuse: diffR(->corr) | baseR | 3 B stages (BK=32) | 2 biases
#define GF_SMEM_W (2 * EF_W + 3 * CH32_W + 256)

// ---------------- weight prep: half Wt[n][permk(k)] = W[k][n] -------------------
__global__ void wprep(const float* __restrict__ W0, const float* __restrict__ W1,
                      const float* __restrict__ W2, const float* __restrict__ W3,
                      __half* __restrict__ T0, __half* __restrict__ T1,
                      __half* __restrict__ T2, __half* __restrict__ T3)
{
    __shared__ float s[32][33];
    int b = blockIdx.x;
    const float* W; __half* T; int K;
    if (b < 8)       { W = W0; T = T0; K = 64;  }
    else if (b < 24) { W = W1; T = T1; K = 128; b -= 8;  }
    else if (b < 56) { W = W2; T = T2; K = 256; b -= 24; }
    else             { W = W3; T = T3; K = 256; b -= 56; }
    const int k0 = (b >> 2) * 32, n0 = (b & 3) * 32;
    const int tx = threadIdx.x & 31, ty = threadIdx.x >> 5;
#pragma unroll
    for (int i = 0; i < 4; i++)
        s[ty + i * 8][tx] = W[(size_t)(k0 + ty + i * 8) * HID + n0 + tx];
    __syncthreads();
    const int k = k0 + tx;
    const int col = ((k >> 4) << 4) + (perm8((k & 15) >> 1) << 1) + (k & 1);
#pragma unroll
    for (int i = 0; i < 4; i++) {
        const int n = n0 + ty + i * 8;
        T[(size_t)n * K + col] = __float2half(s[tx][ty + i * 8]);
    }
}

// ---------------- activation convert: fp32 -> k-permuted fp16 (base only) -------
template<int WPR>
__global__ void cvt_half(const float2* __restrict__ in, uint32_t* __restrict__ out,
                         int total_words)
{
    int idx = blockIdx.x * blockDim.x + threadIdx.x;
    if (idx >= total_words) return;
    const int row = idx / WPR, w = idx % WPR;
    const float2 v = in[idx];
    const __half2 h = __floats2half2_rn(v.x, v.y);
    out[(size_t)row * WPR + permw(w)] = *(const uint32_t*)&h;
}

// ================================================================================
// Fused kernel 1: ef = relu(evR @ Wp + bp) [fp16 smem-resident]; xg = ef @ Wgcn
// (R16 champion, unchanged)
// ================================================================================
__global__ void __launch_bounds__(256, 2)
k_proj_gcn(const float* __restrict__ ev, const __half* __restrict__ Wtp,
           const float* __restrict__ bp, const __half* __restrict__ Wtg,
           uint32_t* __restrict__ xgh, int M)
{
    extern __shared__ uint32_t dsm[];
    uint32_t* ef  = dsm;
    uint32_t* evR = dsm + EF_W;
    uint32_t* Bs  = evR + EV_W;
    float*    sb  = (float*)(Bs + 3 * STG_W);

    const int tid   = threadIdx.x;
    const int wid   = tid >> 5, lane = tid & 31;
    const int warpM = wid & 3,  warpN = wid >> 2;
    const int lr    = lane >> 2, lc = lane & 3;
    const int m0    = blockIdx.x * 128;

    if (tid < 128) sb[tid] = bp[tid];

    const uint32_t bs_b = smem_u32(Bs);

    float c[2][8][4];
#pragma unroll
    for (int mi = 0; mi < 2; mi++)
#pragma unroll
        for (int ni = 0; ni < 8; ni++)
#pragma unroll
            for (int j = 0; j < 4; j++) c[mi][ni][j] = 0.f;

    auto issueB = [&](int st, int ch, const __half* Wt, int WPRW) {
        const int n = tid >> 1, q = tid & 1;
        cp16(bs_b + (uint32_t)(st * STG_W + n * 8 + q * 4) * 4,
             Wt + (size_t)n * (WPRW * 2) + (ch * 8 + q * 4) * 2);
    };

    // ---- B prefetch first (cp.async proceeds while we LDG-convert ev below)
    issueB(0, 0, Wtp, 32); cp_commit();
    issueB(1, 1, Wtp, 32); cp_commit();

    // ---- prologue: load fp32 ev tile, convert to permuted fp16 evR
#pragma unroll
    for (int i = 0; i < 4; i++) {
        const int slot = tid + i * 256;
        const int r = slot >> 3, q = slot & 7;
        int gr = m0 + r; if (gr > M - 1) gr = M - 1;
        const float4 f0 = *(const float4*)(ev + (size_t)gr * 64 + q * 8);
        const float4 f1 = *(const float4*)(ev + (size_t)gr * 64 + q * 8 + 4);
        const __half2 h0 = __floats2half2_rn(f0.x, f0.y);
        const __half2 h1 = __floats2half2_rn(f0.z, f0.w);
        const __half2 h2 = __floats2half2_rn(f1.x, f1.y);
        const __half2 h3 = __floats2half2_rn(f1.z, f1.w);
        evR[r * LDE + permw(q * 4 + 0)] = *(const uint32_t*)&h0;
        evR[r * LDE + permw(q * 4 + 1)] = *(const uint32_t*)&h1;
        evR[r * LDE + permw(q * 4 + 2)] = *(const uint32_t*)&h2;
        evR[r * LDE + permw(q * 4 + 3)] = *(const uint32_t*)&h3;
    }

    auto compute = [&](const uint32_t* Ab, int lda, int wb, const uint32_t* Bb) {
        uint32_t a0[2], a1[2], a2[2], a3[2];
#pragma unroll
        for (int mi = 0; mi < 2; mi++) {
            const int row = warpM * 32 + mi * 16 + lr;
            const uint2 lo = *(const uint2*)(Ab + row * lda + wb + 2 * lc);
            const uint2 hi = *(const uint2*)(Ab + (row + 8) * lda + wb + 2 * lc);
            a0[mi] = lo.x; a1[mi] = hi.x; a2[mi] = lo.y; a3[mi] = hi.y;
        }
#pragma unroll
        for (int ni = 0; ni < 8; ni++) {
            const uint2 bb = *(const uint2*)(Bb + (warpN * 64 + ni * 8 + lr) * 8 + 2 * lc);
#pragma unroll
            for (int mi = 0; mi < 2; mi++)
                mma_f16(c[mi][ni], a0[mi], a1[mi], a2[mi], a3[mi], bb.x, bb.y);
        }
    };

    // ---- phase 1: K=64, 4 B chunks, 3-stage pipeline; A = evR resident
    for (int i = 0; i < 4; i++) {
        if (i < 3) cp_wait<1>(); else cp_wait<0>();
        __syncthreads();
        if (i + 2 < 4) { issueB((i + 2) % 3, i + 2, Wtp, 32); cp_commit(); }
        compute(evR, LDE, i * 8, Bs + (i % 3) * STG_W);
    }
    __syncthreads();

    // prefetch phase-2 B chunks 0,1
    issueB(0, 0, Wtg, 64); cp_commit();
    issueB(1, 1, Wtg, 64); cp_commit();

    // ---- epilogue 1: relu(v+b) -> permuted fp16 into ef
#pragma unroll
    for (int mi = 0; mi < 2; mi++)
#pragma unroll
        for (int half = 0; half < 2; half++) {
            const int row = warpM * 32 + mi * 16 + lr + half * 8;
#pragma unroll
            for (int ni = 0; ni < 8; ni++) {
                const int col = warpN * 64 + ni * 8 + lc * 2;
                const float v0 = fmaxf(c[mi][ni][half * 2 + 0] + sb[col + 0], 0.f);
                const float v1 = fmaxf(c[mi][ni][half * 2 + 1] + sb[col + 1], 0.f);
                const __half2 h = __floats2half2_rn(v0, v1);
                ef[row * LDR + permw(col >> 1)] = *(const uint32_t*)&h;
            }
        }

#pragma unroll
    for (int mi = 0; mi < 2; mi++)
#pragma unroll
        for (int ni = 0; ni < 8; ni++)
#pragma unroll
            for (int j = 0; j < 4; j++) c[mi][ni][j] = 0.f;

    // ---- phase 2: xg = ef @ Wgcn, K=128 (8 chunks), A = ef resident
    for (int i = 0; i < 8; i++) {
        if (i < 7) cp_wait<1>(); else cp_wait<0>();
        __syncthreads();
        if (i + 2 < 8) { issueB((i + 2) % 3, i + 2, Wtg, 64); cp_commit(); }
        compute(ef, LDR, i * 8, Bs + (i % 3) * STG_W);
    }

    // ---- epilogue 2: xg fp16 plain layout
#pragma unroll
    for (int mi = 0; mi < 2; mi++)
#pragma unroll
        for (int half = 0; half < 2; half++) {
            const int row = m0 + warpM * 32 + mi * 16 + lr + half * 8;
            if (row >= M) continue;
#pragma unroll
            for (int ni = 0; ni < 8; ni++) {
                const int col = warpN * 64 + ni * 8 + lc * 2;
                const __half2 h = __floats2half2_rn(c[mi][ni][half * 2 + 0],
                                                    c[mi][ni][half * 2 + 1]);
                xgh[(size_t)row * 64 + (col >> 1)] = *(const uint32_t*)&h;
            }
        }
}

// ================================================================================
// Fused kernel 2: gate GEMM -> corrected (in place over diffR) -> fuse GEMM.
// BK=32 stages (2 sub-tiles each), 3-stage pipeline with cp_wait<1> look-ahead.
// ================================================================================
__global__ void __launch_bounds__(256, 2)
k_gate_fuse(const uint32_t* __restrict__ baseh, const uint32_t* __restrict__ diffh,
            const __half* __restrict__ Wtg, const float* __restrict__ bg,
            const __half* __restrict__ Wtf, const float* __restrict__ bf,
            float* __restrict__ out, int M)
{
    extern __shared__ uint32_t dsm[];
    uint32_t* diffR = dsm;              // overwritten in place by corrected
    uint32_t* baseR = dsm + EF_W;
    uint32_t* Bs    = baseR + EF_W;
    float*    sbg   = (float*)(Bs + 3 * CH32_W);
    float*    sbf   = sbg + 128;

    const int tid   = threadIdx.x;
    const int wid   = tid >> 5, lane = tid & 31;
    const int warpM = wid & 3,  warpN = wid >> 2;
    const int lr    = lane >> 2, lc = lane & 3;
    const int m0    = blockIdx.x * 128;

    if (tid < 128) { sbg[tid] = bg[tid]; sbf[tid] = bf[tid]; }

    const uint32_t df_b = smem_u32(diffR);
    const uint32_t br_b = smem_u32(baseR);
    const uint32_t bs_b = smem_u32(Bs);

    float c[2][8][4];
#pragma unroll
    for (int mi = 0; mi < 2; mi++)
#pragma unroll
        for (int ni = 0; ni < 8; ni++)
#pragma unroll
            for (int j = 0; j < 4; j++) c[mi][ni][j] = 0.f;

    // ---- group 0: whole baseR + diffR tiles (8 cp16/thread each)
    {
        const int r = tid >> 1, q = tid & 1;
        int gr = m0 + r; if (gr > M - 1) gr = M - 1;
#pragma unroll
        for (int c8 = 0; c8 < 8; c8++) {
            cp16(br_b + (uint32_t)(r * LDR + c8 * 8 + q * 4) * 4,
                 baseh + (size_t)gr * 64 + c8 * 8 + q * 4);
            cp16(df_b + (uint32_t)(r * LDR + c8 * 8 + q * 4) * 4,
                 diffh + (size_t)gr * 64 + c8 * 8 + q * 4);
        }
    }
    cp_commit();

    // BK=32 B-chunk copy: 2 sub-tiles per stage (chunk ch covers k-words [ch*16, ch*16+16))
    auto issueB = [&](int st, int ch, const __half* Wt) {
        const int n = tid >> 1, q = tid & 1;
#pragma unroll
        for (int sub = 0; sub < 2; sub++)
            cp16(bs_b + (uint32_t)(st * CH32_W + sub * STG_W + n * 8 + q * 4) * 4,
                 Wt + (size_t)n * 256 + ch * 32 + sub * 16 + q * 8);
    };
    auto compute = [&](const uint32_t* Ab, int wb, const uint32_t* Bb) {
        uint32_t a0[2], a1[2], a2[2], a3[2];
#pragma unroll
        for (int mi = 0; mi < 2; mi++) {
            const int row = warpM * 32 + mi * 16 + lr;
            const uint2 lo = *(const uint2*)(Ab + row * LDR + wb + 2 * lc);
            const uint2 hi = *(const uint2*)(Ab + (row + 8) * LDR + wb + 2 * lc);
            a0[mi] = lo.x; a1[mi] = hi.x; a2[mi] = lo.y; a3[mi] = hi.y;
        }
#pragma unroll
        for (int ni = 0; ni < 8; ni++) {
            const uint2 bb = *(const uint2*)(Bb + (warpN * 64 + ni * 8 + lr) * 8 + 2 * lc);
#pragma unroll
            for (int mi = 0; mi < 2; mi++)
                mma_f16(c[mi][ni], a0[mi], a1[mi], a2[mi], a3[mi], bb.x, bb.y);
        }
    };

    // ---- phase A: gate GEMM, K=256 -> 8 BK=32 chunks; A = baseR then diffR
    issueB(0, 0, Wtg); cp_commit();
    issueB(1, 1, Wtg); cp_commit();
    for (int i = 0; i < 8; i++) {
        if (i < 7) cp_wait<1>(); else cp_wait<0>();
        __syncthreads();
        if (i + 2 < 8) { issueB((i + 2) % 3, i + 2, Wtg); cp_commit(); }
        const uint32_t* Bst = Bs + (i % 3) * CH32_W;
        if (i < 4) {
            compute(baseR, i * 16,     Bst);
            compute(baseR, i * 16 + 8, Bst + STG_W);
        } else {
            compute(diffR, (i - 4) * 16,     Bst);
            compute(diffR, (i - 4) * 16 + 8, Bst + STG_W);
        }
    }
    __syncthreads();

    // prefetch fuse B chunks 0,1
    issueB(0, 0, Wtf); cp_commit();
    issueB(1, 1, Wtf); cp_commit();

    // ---- gate epilogue: corr = base + g*(diff-base), in place over diffR (smem)
#pragma unroll
    for (int mi = 0; mi < 2; mi++)
#pragma unroll
        for (int half = 0; half < 2; half++) {
            const int lrow = warpM * 32 + mi * 16 + lr + half * 8;
#pragma unroll
            for (int ni = 0; ni < 8; ni++) {
                const int col = warpN * 64 + ni * 8 + lc * 2;
                const int pw  = permw(col >> 1);
                const uint32_t ub = baseR[lrow * LDR + pw];
                const uint32_t ud = diffR[lrow * LDR + pw];
                const float2 b2 = __half22float2(*(const __half2*)&ub);
                const float2 d2 = __half22float2(*(const __half2*)&ud);
                const float g0 = 1.f / (1.f + __expf(-(c[mi][ni][half * 2 + 0] + sbg[col + 0])));
                const float g1 = 1.f / (1.f + __expf(-(c[mi][ni][half * 2 + 1] + sbg[col + 1])));
                const float v0 = fmaf(d2.x - b2.x, g0, b2.x);
                const float v1 = fmaf(d2.y - b2.y, g1, b2.y);
                const __half2 h = __floats2half2_rn(v0, v1);
                diffR[lrow * LDR + pw] = *(const uint32_t*)&h;
            }
        }

#pragma unroll
    for (int mi = 0; mi < 2; mi++)
#pragma unroll
        for (int ni = 0; ni < 8; ni++)
#pragma unroll
            for (int j = 0; j < 4; j++) c[mi][ni][j] = 0.f;

    // ---- phase B: fuse GEMM, K=256 -> 8 BK=32 chunks; A = baseR then corr(diffR)
    for (int i = 0; i < 8; i++) {
        if (i < 7) cp_wait<1>(); else cp_wait<0>();
        __syncthreads();                    // orders corr writes at i=0
        if (i + 2 < 8) { issueB((i + 2) % 3, i + 2, Wtf); cp_commit(); }
        const uint32_t* Bst = Bs + (i % 3) * CH32_W;
        if (i < 4) {
            compute(baseR, i * 16,     Bst);
            compute(baseR, i * 16 + 8, Bst + STG_W);
        } else {
            compute(diffR, (i - 4) * 16,     Bst);
            compute(diffR, (i - 4) * 16 + 8, Bst + STG_W);
        }
    }

    // ---- fuse epilogue: relu(v + bf) -> out (fp32)
#pragma unroll
    for (int mi = 0; mi < 2; mi++)
#pragma unroll
        for (int half = 0; half < 2; half++) {
            const int row = m0 + warpM * 32 + mi * 16 + lr + half * 8;
            if (row >= M) continue;
#pragma unroll
            for (int ni = 0; ni < 8; ni++) {
                const int col = warpN * 64 + ni * 8 + lc * 2;
                *(float2*)(out + (size_t)row * HID + col) =
                    make_float2(fmaxf(c[mi][ni][half * 2 + 0] + sbf[col + 0], 0.f),
                                fmaxf(c[mi][ni][half * 2 + 1] + sbf[col + 1], 0.f));
            }
        }
}

// ---------------- per-block edge-dtype detection --------------------------------
__device__ __forceinline__ int detect_is32(const void* ei) {
    const unsigned* p = (const unsigned*)ei;
    int any = 0;
    for (int i = threadIdx.x; i < 256; i += blockDim.x)
        any |= (p[2 * i + 1] != 0u);
    return __syncthreads_or(any);
}

// ---------------- degree / CSR (1 edge/thread — atomic-parallel) ------------------
__global__ void count_deg(const void* __restrict__ ei, int E) {
    const int is32 = detect_is32(ei);
    int e = blockIdx.x * blockDim.x + threadIdx.x;
    if (e >= E) return;
    int d = is32 ? ((const int*)ei)[(size_t)E + e]
                 : (int)((const long long*)ei)[(size_t)E + e];
    atomicAdd(&g_deg[d], 1);
}
__global__ void scan1(int n) {
    __shared__ int sh[512];
    int i = blockIdx.x * 512 + threadIdx.x;
    int v = (i < n) ? g_deg[i] : 0;
    if (i < n) g_dis[i] = rsqrtf((float)(v + 1));
    sh[threadIdx.x] = v;
    __syncthreads();
    for (int off = 256; off > 0; off >>= 1) {
        if (threadIdx.x < off) sh[threadIdx.x] += sh[threadIdx.x + off];
        __syncthreads();
    }
    if (threadIdx.x == 0) g_bsum[blockIdx.x] = sh[0];
}
__global__ void scan2(int nb) {
    __shared__ int sh[1024];
    int tid = threadIdx.x;
    int v = (tid < nb) ? g_bsum[tid] : 0;
    sh[tid] = v;
    __syncthreads();
    for (int off = 1; off < 1024; off <<= 1) {
        int t = (tid >= off) ? sh[tid - off] : 0;
        __syncthreads();
        sh[tid] += t;
        __syncthreads();
    }
    if (tid < nb) g_bsum[tid] = sh[tid] - v;
}
__global__ void scan3(int n) {
    __shared__ int sh[512];
    int tid = threadIdx.x;
    int i = blockIdx.x * 512 + tid;
    int v = (i < n) ? g_deg[i] : 0;
    sh[tid] = v;
    __syncthreads();
    for (int off = 1; off < 512; off <<= 1) {
        int t = (tid >= off) ? sh[tid - off] : 0;
        __syncthreads();
        sh[tid] += t;
        __syncthreads();
    }
    if (i < n) {
        int rs = g_bsum[blockIdx.x] + sh[tid] - v;
        g_rowstart[i] = rs;
        g_cursor[i]   = rs;
    }
}
__global__ void fill_csr(const void* __restrict__ ei, int E) {
    const int is32 = detect_is32(ei);
    int e = blockIdx.x * blockDim.x + threadIdx.x;
    if (e >= E) return;
    int s, d;
    if (is32) {
        s = ((const int*)ei)[e];
        d = ((const int*)ei)[(size_t)E + e];
    } else {
        s = (int)((const long long*)ei)[e];
        d = (int)((const long long*)ei)[(size_t)E + e];
    }
    int pos = atomicAdd(&g_cursor[d], 1);
    g_csr[pos] = s;
}

// ---------------- aggregation: warp per node, 2-way edge ILP ---------------------
__device__ __forceinline__ float4 h4f(uint2 v) {
    const float2 f0 = __half22float2(*(const __half2*)&v.x);
    const float2 f1 = __half22float2(*(const __half2*)&v.y);
    return make_float4(f0.x, f0.y, f1.x, f1.y);
}
__global__ void aggregate(const float* __restrict__ b_gcn, int n) {
    int gw   = (blockIdx.x * blockDim.x + threadIdx.x) >> 5;
    int lane = threadIdx.x & 31;
    if (gw >= n) return;
    const int node = gw;
    const uint2* __restrict__ xg2 = (const uint2*)g_xgh;

    const float4 selfv = h4f(xg2[(size_t)node * 32 + lane]);
    const float  dn    = g_dis[node];
    const int    s0    = g_rowstart[node];
    const int    cnt   = g_deg[node];

    float4 acc = make_float4(0.f, 0.f, 0.f, 0.f);
    int e = s0, eend = s0 + cnt;
    for (; e + 1 < eend; e += 2) {
        const int s1 = g_csr[e], s2 = g_csr[e + 1];
        const float w1 = g_dis[s1], w2 = g_dis[s2];
        const float4 v1 = h4f(xg2[(size_t)s1 * 32 + lane]);
        const float4 v2 = h4f(xg2[(size_t)s2 * 32 + lane]);
        acc.x += v1.x * w1 + v2.x * w2;
        acc.y += v1.y * w1 + v2.y * w2;
        acc.z += v1.z * w1 + v2.z * w2;
        acc.w += v1.w * w1 + v2.w * w2;
    }
    if (e < eend) {
        const int s1 = g_csr[e];
        const float w1 = g_dis[s1];
        const float4 v1 = h4f(xg2[(size_t)s1 * 32 + lane]);
        acc.x += v1.x * w1; acc.y += v1.y * w1;
        acc.z += v1.z * w1; acc.w += v1.w * w1;
    }
    const float sw = dn * dn;
    const float4 b = ((const float4*)b_gcn)[lane];
    float4 o;
    o.x = fmaxf(acc.x * dn + selfv.x * sw + b.x, 0.f);
    o.y = fmaxf(acc.y * dn + selfv.y * sw + b.y, 0.f);
    o.z = fmaxf(acc.z * dn + selfv.z * sw + b.z, 0.f);
    o.w = fmaxf(acc.w * dn + selfv.w * sw + b.w, 0.f);
    const __half2 h0 = __floats2half2_rn(o.x, o.y);
    const __half2 h1 = __floats2half2_rn(o.z, o.w);
    uint32_t* drow = g_diffh + (size_t)node * 64;
    drow[permw(2 * lane)]     = *(const uint32_t*)&h0;
    drow[permw(2 * lane + 1)] = *(const uint32_t*)&h1;
}

// ---------------- launcher --------------------------------------------------------
extern "C" void kernel_launch(void* const* d_in, const int* in_sizes, int n_in,
                              void* d_out, int out_size)
{
    const float* base   = (const float*)d_in[0];
    const float* ev     = (const float*)d_in[1];
    const void*  ei     = d_in[2];
    const float* W_proj = (const float*)d_in[3];
    const float* b_proj = (const float*)d_in[4];
    const float* W_gcn  = (const float*)d_in[5];
    const float* b_gcn  = (const float*)d_in[6];
    const float* W_gate = (const float*)d_in[7];
    const float* b_gate = (const float*)d_in[8];
    const float* W_fuse = (const float*)d_in[9];
    const float* b_fuse = (const float*)d_in[10];

    const int N = in_sizes[0] / HID;
    const int E = in_sizes[2] / 2;

    uint32_t *p_xgh, *p_diffh, *p_baseh;
    __half *p_wtp, *p_wtg, *p_wtga, *p_wtf;
    int *p_deg;
    cudaGetSymbolAddress((void**)&p_xgh,   g_xgh);
    cudaGetSymbolAddress((void**)&p_diffh, g_diffh);
    cudaGetSymbolAddress((void**)&p_baseh, g_baseh);
    cudaGetSymbolAddress((void**)&p_wtp,   g_wt_proj);
    cudaGetSymbolAddress((void**)&p_wtg,   g_wt_gcn);
    cudaGetSymbolAddress((void**)&p_wtga,  g_wt_gate);
    cudaGetSymbolAddress((void**)&p_wtf,   g_wt_fuse);
    cudaGetSymbolAddress((void**)&p_deg,   g_deg);

    cudaFuncSetAttribute(k_proj_gcn,  cudaFuncAttributeMaxDynamicSharedMemorySize, PG_SMEM_W * 4);
    cudaFuncSetAttribute(k_gate_fuse, cudaFuncAttributeMaxDynamicSharedMemorySize, GF_SMEM_W * 4);

    const int gT = (N + 127) / 128;
    const int gE = (E + 255) / 256;
    const int nb = (N + 511) / 512;

    // single side stream for CSR chain + base convert (destroyed before return)
    cudaStream_t side;
    cudaEvent_t evFork, evJoin, evJoin2;
    cudaStreamCreateWithFlags(&side, cudaStreamNonBlocking);
    cudaEventCreateWithFlags(&evFork,  cudaEventDisableTiming);
    cudaEventCreateWithFlags(&evJoin,  cudaEventDisableTiming);
    cudaEventCreateWithFlags(&evJoin2, cudaEventDisableTiming);

    cudaEventRecord(evFork, 0);
    cudaStreamWaitEvent(side, evFork, 0);

    // --- side: CSR build, then base convert (joined separately)
    cudaMemsetAsync(p_deg, 0, (size_t)N * sizeof(int), side);
    count_deg<<<gE, 256, 0, side>>>(ei, E);
    scan1<<<nb, 512, 0, side>>>(N);
    scan2<<<1, 1024, 0, side>>>(nb);
    scan3<<<nb, 512, 0, side>>>(N);
    fill_csr<<<gE, 256, 0, side>>>(ei, E);
    cudaEventRecord(evJoin, side);                      // CSR ready
    cvt_half<64><<<(N * 64 + 255) / 256, 256, 0, side>>>((const float2*)base, p_baseh, N * 64);
    cudaEventRecord(evJoin2, side);                     // baseh ready

    // --- main: weight prep + fused proj/gcn GEMM (ev converted in-kernel)
    wprep<<<88, 256>>>(W_proj, W_gcn, W_gate, W_fuse, p_wtp, p_wtg, p_wtga, p_wtf);
    k_proj_gcn<<<gT, 256, PG_SMEM_W * 4>>>(ev, p_wtp, b_proj, p_wtg, p_xgh, N);

    // aggregate needs xgh (main) + CSR (side); overlaps cvt_base on the side stream
    cudaStreamWaitEvent(0, evJoin, 0);
    aggregate<<<(N * 32 + 255) / 256, 256>>>(b_gcn, N);

    // gate_fuse additionally needs baseh
    cudaStreamWaitEvent(0, evJoin2, 0);
    k_gate_fuse<<<gT, 256, GF_SMEM_W * 4>>>(p_baseh, p_diffh, p_wtga, b_gate,
                                            p_wtf, b_fuse, (float*)d_out, N);

    // release resources created this call (graph retains captured dependencies)
    cudaEventDestroy(evFork);
    cudaEventDestroy(evJoin);
    cudaEventDestroy(evJoin2);
    cudaStreamDestroy(side);
}